// round 1
// baseline (speedup 1.0000x reference)
#include <cuda_runtime.h>

// Problem constants
#define NBODY   10
#define NPAIRS  90          // B*(B-1)
#define HID     128
#define TILE    128         // rows per block
#define NTHREADS 512
#define HPAD    132         // padded row stride for activation tile (bank-conflict-free)
#define SELF_ROWS  81920    // N*B
#define INT_ROWS   737280   // N*B*(B-1)

// scratch for per-pair interaction outputs (no allocs allowed -> device global)
__device__ float g_scratch[INT_ROWS * 4];

__device__ __forceinline__ float softplus_f(float x) {
    // max(x,0) + log1p(exp(-|x|)); log1p via fast log(1+e): abs err ~1e-7, fine at 1e-3 tol
    float e = __expf(-fabsf(x));
    return fmaxf(x, 0.0f) + __logf(1.0f + e);
}

// Fused 3-layer MLP over a 128-row tile.
// NIN==4: self MLP, input = z rows directly, output -> out (d_out)
// NIN==6: interaction MLP, input built from (rec,send) pair of z rows, output -> g_scratch
template <int NIN>
__global__ __launch_bounds__(NTHREADS, 1)
void mlp_kernel(const float* __restrict__ z,
                const float* __restrict__ W0, const float* __restrict__ b0,
                const float* __restrict__ W1, const float* __restrict__ b1,
                const float* __restrict__ W2, const float* __restrict__ b2,
                float* __restrict__ out)
{
    extern __shared__ float smem[];
    float* W1s  = smem;                      // 128*128
    float* Hs   = W1s + HID * HID;           // 128*HPAD (h0, then reused for h1)
    float* INPs = Hs + TILE * HPAD;          // 128*8
    float* W0s  = INPs + TILE * 8;           // 8*128 (only NIN rows used)
    float* W2t  = W0s + 8 * HID;             // 4*HPAD (transposed W2)
    float* b0s  = W2t + 4 * HPAD;            // 128
    float* b1s  = b0s + HID;                 // 128
    float* b2s  = b1s + HID;                 // 4

    const int tid = threadIdx.x;
    const int rowBase = blockIdx.x * TILE;

    // ---- stage weights ----
    for (int i = tid; i < HID * HID / 4; i += NTHREADS)
        ((float4*)W1s)[i] = ((const float4*)W1)[i];
    for (int i = tid; i < NIN * HID / 4; i += NTHREADS)
        ((float4*)W0s)[i] = ((const float4*)W0)[i];
    if (tid < HID) { b0s[tid] = b0[tid]; b1s[tid] = b1[tid]; }
    if (tid < 4)   b2s[tid] = b2[tid];
    for (int i = tid; i < HID * 4; i += NTHREADS) {
        int k = i >> 2, c = i & 3;
        W2t[c * HPAD + k] = W2[i];           // transpose [k][4] -> [c][k]
    }

    // ---- build inputs for this row tile ----
    if (tid < TILE) {
        int grow = rowBase + tid;
        if (NIN == 4) {
            float4 zz = ((const float4*)z)[grow];
            INPs[tid * 8 + 0] = zz.x; INPs[tid * 8 + 1] = zz.y;
            INPs[tid * 8 + 2] = zz.z; INPs[tid * 8 + 3] = zz.w;
        } else {
            int n   = grow / NPAIRS;
            int pr  = grow % NPAIRS;
            int rec = pr / (NBODY - 1);
            int sr  = pr % (NBODY - 1);
            int snd = sr + (sr >= rec ? 1 : 0);
            float4 zr = ((const float4*)z)[n * NBODY + rec];
            float4 zs = ((const float4*)z)[n * NBODY + snd];
            INPs[tid * 8 + 0] = zr.x - zs.x;
            INPs[tid * 8 + 1] = zr.y - zs.y;
            INPs[tid * 8 + 2] = zr.z;
            INPs[tid * 8 + 3] = zr.w;
            INPs[tid * 8 + 4] = zs.z;
            INPs[tid * 8 + 5] = zs.w;
        }
    }
    __syncthreads();

    // ---- layer 0: h0 = softplus(inp @ W0 + b0) ----
    #pragma unroll 1
    for (int i = tid; i < TILE * HID; i += NTHREADS) {
        int r = i >> 7, c = i & 127;
        float acc = b0s[c];
        #pragma unroll
        for (int j = 0; j < NIN; j++)
            acc += INPs[r * 8 + j] * W0s[j * HID + c];
        Hs[r * HPAD + c] = softplus_f(acc);
    }
    __syncthreads();

    // ---- layer 1: h1 = softplus(h0 @ W1 + b1), 8x4 register tile / thread ----
    const int tx = tid & 31;   // col group: cols tx*4 .. tx*4+3
    const int ty = tid >> 5;   // row group: rows ty*8 .. ty*8+7 (warp-uniform -> a-frag broadcast)
    float acc[8][4];
    {
        float4 bv = *(const float4*)&b1s[tx * 4];
        #pragma unroll
        for (int r = 0; r < 8; r++) {
            acc[r][0] = bv.x; acc[r][1] = bv.y; acc[r][2] = bv.z; acc[r][3] = bv.w;
        }
    }
    #pragma unroll 1
    for (int k0 = 0; k0 < HID; k0 += 4) {
        float4 w0v = *(const float4*)&W1s[(k0 + 0) * HID + tx * 4];
        float4 w1v = *(const float4*)&W1s[(k0 + 1) * HID + tx * 4];
        float4 w2v = *(const float4*)&W1s[(k0 + 2) * HID + tx * 4];
        float4 w3v = *(const float4*)&W1s[(k0 + 3) * HID + tx * 4];
        #pragma unroll
        for (int r = 0; r < 8; r++) {
            float4 av = *(const float4*)&Hs[(ty * 8 + r) * HPAD + k0];
            acc[r][0] += av.x * w0v.x; acc[r][1] += av.x * w0v.y;
            acc[r][2] += av.x * w0v.z; acc[r][3] += av.x * w0v.w;
            acc[r][0] += av.y * w1v.x; acc[r][1] += av.y * w1v.y;
            acc[r][2] += av.y * w1v.z; acc[r][3] += av.y * w1v.w;
            acc[r][0] += av.z * w2v.x; acc[r][1] += av.z * w2v.y;
            acc[r][2] += av.z * w2v.z; acc[r][3] += av.z * w2v.w;
            acc[r][0] += av.w * w3v.x; acc[r][1] += av.w * w3v.y;
            acc[r][2] += av.w * w3v.z; acc[r][3] += av.w * w3v.w;
        }
    }
    __syncthreads();   // everyone done reading h0 before overwrite

    #pragma unroll
    for (int r = 0; r < 8; r++) {
        float4 v;
        v.x = softplus_f(acc[r][0]);
        v.y = softplus_f(acc[r][1]);
        v.z = softplus_f(acc[r][2]);
        v.w = softplus_f(acc[r][3]);
        *(float4*)&Hs[(ty * 8 + r) * HPAD + tx * 4] = v;   // h1, contiguous per warp
    }
    __syncthreads();

    // ---- layer 2: out = h1 @ W2 + b2 (one output scalar per thread) ----
    {
        int row = tid >> 2, c = tid & 3;
        float a2 = b2s[c];
        #pragma unroll 4
        for (int k0 = 0; k0 < HID; k0 += 4) {
            float4 h = *(const float4*)&Hs[row * HPAD + k0];
            float4 w = *(const float4*)&W2t[c * HPAD + k0];
            a2 += h.x * w.x + h.y * w.y + h.z * w.z + h.w * w.w;
        }
        float* dst = (NIN == 6) ? g_scratch : out;
        dst[(rowBase + row) * 4 + c] = a2;   // coalesced
    }
}

// out[n,rec,:] += sum_{j=0..8} scratch[n*90 + rec*9 + j, :]
__global__ void reduce_kernel(float* __restrict__ out)
{
    int r = blockIdx.x * blockDim.x + threadIdx.x;
    if (r >= SELF_ROWS) return;
    int n = r / NBODY, rec = r % NBODY;
    const float4* sc = (const float4*)g_scratch;
    int base = n * NPAIRS + rec * (NBODY - 1);
    float4 s = sc[base];
    #pragma unroll
    for (int j = 1; j < NBODY - 1; j++) {
        float4 t = sc[base + j];
        s.x += t.x; s.y += t.y; s.z += t.z; s.w += t.w;
    }
    float4 o = ((float4*)out)[r];
    o.x += s.x; o.y += s.y; o.z += s.z; o.w += s.w;
    ((float4*)out)[r] = o;
}

extern "C" void kernel_launch(void* const* d_in, const int* in_sizes, int n_in,
                              void* d_out, int out_size)
{
    const float* z   = (const float*)d_in[0];
    const float* fW0 = (const float*)d_in[1];
    const float* fb0 = (const float*)d_in[2];
    const float* fW1 = (const float*)d_in[3];
    const float* fb1 = (const float*)d_in[4];
    const float* fW2 = (const float*)d_in[5];
    const float* fb2 = (const float*)d_in[6];
    const float* iW0 = (const float*)d_in[7];
    const float* ib0 = (const float*)d_in[8];
    const float* iW1 = (const float*)d_in[9];
    const float* ib1 = (const float*)d_in[10];
    const float* iW2 = (const float*)d_in[11];
    const float* ib2 = (const float*)d_in[12];
    float* out = (float*)d_out;

    // dynamic smem: W1s + Hs + INPs + W0s + W2t + b0 + b1 + b2
    size_t smem = (size_t)(HID * HID + TILE * HPAD + TILE * 8 + 8 * HID
                           + 4 * HPAD + HID + HID + 4) * sizeof(float);

    cudaFuncSetAttribute(mlp_kernel<4>, cudaFuncAttributeMaxDynamicSharedMemorySize, (int)smem);
    cudaFuncSetAttribute(mlp_kernel<6>, cudaFuncAttributeMaxDynamicSharedMemorySize, (int)smem);

    // self MLP -> d_out
    mlp_kernel<4><<<SELF_ROWS / TILE, NTHREADS, smem>>>(z, fW0, fb0, fW1, fb1, fW2, fb2, out);
    // interaction MLP -> g_scratch
    mlp_kernel<6><<<INT_ROWS / TILE, NTHREADS, smem>>>(z, iW0, ib0, iW1, ib1, iW2, ib2, nullptr);
    // sum 9 senders per receiver and add to self output
    reduce_kernel<<<(SELF_ROWS + 255) / 256, 256>>>(out);
}

// round 3
// speedup vs baseline: 2.6090x; 2.6090x over previous
#include <cuda_runtime.h>
#include <cstdint>

// ---------------- problem constants ----------------
#define NBODY     10
#define NPAIRS    90
#define HID       128
#define TILE      128
#define SELF_ROWS 81920
#define INT_ROWS  737280
#define SELF_TILES (SELF_ROWS / TILE)   // 640
#define INT_TILES  (INT_ROWS / TILE)    // 5760
#define NCTA      148
#define NTHREADS  512                   // 2 tile-streams of 256 threads
#define S         136                   // smem row stride (floats): conflict-free frags

// smem byte offsets
#define OFF_W1T   0          // 128 x S fp32 (tf32-rounded), [n][pos(k)]   69632 B
#define OFF_A0    69632      // tile-stream 0 H0 buffer 128 x S            69632 B
#define OFF_A1    139264     // tile-stream 1                              69632 B
#define OFF_P0    208896     // stream 0: inp overlay (4KB) / partials 8KB
#define OFF_P1    217088
#define OFF_W0    225280     // up to 6*128 fp32
#define OFF_B0    228352     // 128 fp32
#define OFF_B1    228864     // 128 fp32
#define OFF_W2    229376     // 128x4 fp32
#define OFF_B2    231424     // 4 fp32
#define SMEM_TOTAL 231456

__device__ float g_scratch[INT_ROWS * 4];

// ---------------- helpers ----------------
__device__ __forceinline__ float f2tf32f(float x) {
    uint32_t v; asm("cvt.rna.tf32.f32 %0, %1;" : "=r"(v) : "f"(x));
    return __uint_as_float(v);
}
__device__ __forceinline__ float softplus_f(float x) {
    float e = __expf(-fabsf(x));
    return fmaxf(x, 0.0f) + __logf(1.0f + e);
}
// permute cols within each 8-group so (c, c+4) are adjacent: frag loads = uint2
__device__ __forceinline__ int pos8(int c) {
    return (c & ~7) | ((c & 3) << 1) | ((c >> 2) & 1);
}
__device__ __forceinline__ void mma_tf32(float* c, uint32_t a0, uint32_t a1,
                                         uint32_t a2, uint32_t a3,
                                         uint32_t b0, uint32_t b1) {
    asm("mma.sync.aligned.m16n8k8.row.col.f32.tf32.tf32.f32 "
        "{%0,%1,%2,%3}, {%4,%5,%6,%7}, {%8,%9}, {%0,%1,%2,%3};"
        : "+f"(c[0]), "+f"(c[1]), "+f"(c[2]), "+f"(c[3])
        : "r"(a0), "r"(a1), "r"(a2), "r"(a3), "r"(b0), "r"(b1));
}

// ---------------- fused persistent MLP ----------------
template <int NIN>
__global__ __launch_bounds__(NTHREADS, 1)
void mlp_mma(const float* __restrict__ z,
             const float* __restrict__ W0, const float* __restrict__ b0,
             const float* __restrict__ W1, const float* __restrict__ b1,
             const float* __restrict__ W2, const float* __restrict__ b2,
             float* __restrict__ out_direct, int ntiles)
{
    extern __shared__ __align__(16) char smem[];
    float* W1t = (float*)(smem + OFF_W1T);
    float* W0s = (float*)(smem + OFF_W0);
    float* b0s = (float*)(smem + OFF_B0);
    float* b1s = (float*)(smem + OFF_B1);
    const float4* W2v = (const float4*)(smem + OFF_W2);
    float* b2s = (float*)(smem + OFF_B2);

    const int tid = threadIdx.x;
    float* out = (NIN == 6) ? g_scratch : out_direct;

    // ---- stage weights once ----
    for (int i = tid; i < HID * HID; i += NTHREADS) {
        int k = i >> 7, n = i & 127;
        W1t[n * S + pos8(k)] = f2tf32f(W1[i]);      // B as [n][pos(k)] (col layout)
    }
    for (int i = tid; i < NIN * HID; i += NTHREADS) W0s[i] = W0[i];
    if (tid < HID) { b0s[tid] = b0[tid]; b1s[tid] = b1[tid]; }
    for (int i = tid; i < HID * 4; i += NTHREADS) ((float*)(smem + OFF_W2))[i] = W2[i];
    if (tid < 4) b2s[tid] = b2[tid];
    __syncthreads();

    const int wg   = tid >> 8;            // tile stream 0/1
    const int wt   = tid & 255;
    const int w8   = wt >> 5;             // warp in stream: 0..7
    const int lane = tid & 31;
    const int g    = lane >> 2;           // frag group row
    const int j    = lane & 3;            // frag thread-in-group
    const int mi   = w8 >> 2;             // 0/1: rows mi*64..+63
    const int ni   = w8 & 3;              // 0..3: cols ni*32..+31

    float* As  = (float*)(smem + OFF_A0 + wg * 69632);
    float* P   = (float*)(smem + OFF_P0 + wg * 8192);
    float* inp = P;                       // overlay: dead before partials are written
    const int wbar = 1 + wg;

    const float4 b2v = *(const float4*)b2s;

    // layer0 per-thread constants (thread = column col, row-half wt>>7)
    const int col   = wt & 127;
    const int rbase = (wt >> 7) * 64;
    float w0r[NIN];
    #pragma unroll
    for (int q = 0; q < NIN; q++) w0r[q] = W0s[q * HID + col];
    const float b0c = b0s[col];
    const int   pc  = pos8(col);

    const int r0 = mi * 64, n0 = ni * 32;

    for (int t = blockIdx.x * 2 + wg; t < ntiles; t += gridDim.x * 2) {
        const int rowBase = t * TILE;

        // ---- build 128 input rows ----
        if (wt < 128) {
            int grow = rowBase + wt;
            if (NIN == 4) {
                float4 zz = ((const float4*)z)[grow];
                inp[wt * 8 + 0] = zz.x; inp[wt * 8 + 1] = zz.y;
                inp[wt * 8 + 2] = zz.z; inp[wt * 8 + 3] = zz.w;
            } else {
                int n   = grow / NPAIRS;
                int pr  = grow - n * NPAIRS;
                int rec = pr / (NBODY - 1);
                int sr  = pr - rec * (NBODY - 1);
                int snd = sr + (sr >= rec ? 1 : 0);
                float4 zr = ((const float4*)z)[n * NBODY + rec];
                float4 zs = ((const float4*)z)[n * NBODY + snd];
                inp[wt * 8 + 0] = zr.x - zs.x;
                inp[wt * 8 + 1] = zr.y - zs.y;
                inp[wt * 8 + 2] = zr.z;
                inp[wt * 8 + 3] = zr.w;
                inp[wt * 8 + 4] = zs.z;
                inp[wt * 8 + 5] = zs.w;
            }
        }
        asm volatile("bar.sync %0, 256;" :: "r"(wbar) : "memory");

        // ---- layer 0: As[r][pos(col)] = tf32(softplus(inp[r].W0[:,col]+b0)) ----
        #pragma unroll 4
        for (int r = 0; r < 64; r++) {
            const float* ip = inp + (rbase + r) * 8;
            float a = b0c;
            #pragma unroll
            for (int q = 0; q < NIN; q++) a += ip[q] * w0r[q];
            As[(rbase + r) * S + pc] = f2tf32f(softplus_f(a));
        }
        asm volatile("bar.sync %0, 256;" :: "r"(wbar) : "memory");

        // ---- layer 1: 64x32 warp tile, m16n8k8 tf32 mma ----
        float c[4][4][4];
        #pragma unroll
        for (int mt = 0; mt < 4; mt++)
            #pragma unroll
            for (int nt = 0; nt < 4; nt++)
                #pragma unroll
                for (int q = 0; q < 4; q++) c[mt][nt][q] = 0.0f;

        #pragma unroll 1
        for (int k = 0; k < 16; k++) {
            const int kb = k * 8 + 2 * j;
            uint2 bf[4], a0v[4], a1v[4];
            #pragma unroll
            for (int nt = 0; nt < 4; nt++)
                bf[nt] = *(const uint2*)&W1t[(n0 + nt * 8 + g) * S + kb];
            #pragma unroll
            for (int mt = 0; mt < 4; mt++) {
                a0v[mt] = *(const uint2*)&As[(r0 + mt * 16 + g) * S + kb];
                a1v[mt] = *(const uint2*)&As[(r0 + mt * 16 + 8 + g) * S + kb];
            }
            #pragma unroll
            for (int mt = 0; mt < 4; mt++)
                #pragma unroll
                for (int nt = 0; nt < 4; nt++)
                    mma_tf32(c[mt][nt], a0v[mt].x, a1v[mt].x, a0v[mt].y, a1v[mt].y,
                             bf[nt].x, bf[nt].y);
        }

        // ---- epilogue: h1 = softplus(D + b1); partial = h1 @ W2 ----
        float  b1r[8];
        float4 w2r[8];
        #pragma unroll
        for (int nt = 0; nt < 4; nt++)
            #pragma unroll
            for (int kk = 0; kk < 2; kk++) {
                int cc = n0 + nt * 8 + 2 * j + kk;
                b1r[nt * 2 + kk] = b1s[cc];
                w2r[nt * 2 + kk] = W2v[cc];
            }
        #pragma unroll
        for (int mt = 0; mt < 4; mt++) {
            #pragma unroll
            for (int rr = 0; rr < 2; rr++) {
                float4 p = make_float4(0.f, 0.f, 0.f, 0.f);
                #pragma unroll
                for (int nt = 0; nt < 4; nt++)
                    #pragma unroll
                    for (int kk = 0; kk < 2; kk++) {
                        float h = softplus_f(c[mt][nt][rr * 2 + kk] + b1r[nt * 2 + kk]);
                        float4 wv = w2r[nt * 2 + kk];
                        p.x += h * wv.x; p.y += h * wv.y;
                        p.z += h * wv.z; p.w += h * wv.w;
                    }
                #pragma unroll
                for (int msk = 1; msk <= 2; msk <<= 1) {
                    p.x += __shfl_xor_sync(0xffffffffu, p.x, msk);
                    p.y += __shfl_xor_sync(0xffffffffu, p.y, msk);
                    p.z += __shfl_xor_sync(0xffffffffu, p.z, msk);
                    p.w += __shfl_xor_sync(0xffffffffu, p.w, msk);
                }
                if (j == 0) {
                    int row = r0 + mt * 16 + rr * 8 + g;
                    *(float4*)&P[(ni * 128 + row) * 4] = p;
                }
            }
        }
        asm volatile("bar.sync %0, 256;" :: "r"(wbar) : "memory");

        if (wt < 128) {
            const float4* P4 = (const float4*)P;
            float4 o = b2v;
            #pragma unroll
            for (int q = 0; q < 4; q++) {
                float4 v = P4[q * 128 + wt];
                o.x += v.x; o.y += v.y; o.z += v.z; o.w += v.w;
            }
            ((float4*)out)[rowBase + wt] = o;
        }
        asm volatile("bar.sync %0, 256;" :: "r"(wbar) : "memory");
    }
}

// out[n,rec,:] += sum_{j} scratch[n*90 + rec*9 + j, :]
__global__ void reduce_kernel(float* __restrict__ out)
{
    int r = blockIdx.x * blockDim.x + threadIdx.x;
    if (r >= SELF_ROWS) return;
    int n = r / NBODY, rec = r - n * NBODY;
    const float4* sc = (const float4*)g_scratch;
    int base = n * NPAIRS + rec * (NBODY - 1);
    float4 s = sc[base];
    #pragma unroll
    for (int q = 1; q < NBODY - 1; q++) {
        float4 v = sc[base + q];
        s.x += v.x; s.y += v.y; s.z += v.z; s.w += v.w;
    }
    float4 o = ((float4*)out)[r];
    o.x += s.x; o.y += s.y; o.z += s.z; o.w += s.w;
    ((float4*)out)[r] = o;
}

extern "C" void kernel_launch(void* const* d_in, const int* in_sizes, int n_in,
                              void* d_out, int out_size)
{
    const float* z   = (const float*)d_in[0];
    const float* fW0 = (const float*)d_in[1];
    const float* fb0 = (const float*)d_in[2];
    const float* fW1 = (const float*)d_in[3];
    const float* fb1 = (const float*)d_in[4];
    const float* fW2 = (const float*)d_in[5];
    const float* fb2 = (const float*)d_in[6];
    const float* iW0 = (const float*)d_in[7];
    const float* ib0 = (const float*)d_in[8];
    const float* iW1 = (const float*)d_in[9];
    const float* ib1 = (const float*)d_in[10];
    const float* iW2 = (const float*)d_in[11];
    const float* ib2 = (const float*)d_in[12];
    float* out = (float*)d_out;

    cudaFuncSetAttribute(mlp_mma<4>, cudaFuncAttributeMaxDynamicSharedMemorySize, SMEM_TOTAL);
    cudaFuncSetAttribute(mlp_mma<6>, cudaFuncAttributeMaxDynamicSharedMemorySize, SMEM_TOTAL);

    mlp_mma<4><<<NCTA, NTHREADS, SMEM_TOTAL>>>(z, fW0, fb0, fW1, fb1, fW2, fb2,
                                               out, SELF_TILES);
    mlp_mma<6><<<NCTA, NTHREADS, SMEM_TOTAL>>>(z, iW0, ib0, iW1, ib1, iW2, ib2,
                                               nullptr, INT_TILES);
    reduce_kernel<<<(SELF_ROWS + 255) / 256, 256>>>(out);
}